// round 6
// baseline (speedup 1.0000x reference)
#include <cuda_runtime.h>
#include <math.h>

#define N_NET 16
#define HID   32

// 8-byte result slot (device global: allocation-free scratch).
__device__ float g_probs[2];

// ---------------------------------------------------------------------------
// Primary: 1 block, 16 warps. Warp k evaluates MLP k on s[0][k%4]; thread 0
// reduces to the 2-way softmax and publishes g_probs, then all threads
// trigger programmatic launch completion so the fill grid can proceed.
// ---------------------------------------------------------------------------
__global__ __launch_bounds__(512, 1)
void controller_compute_kernel(const float* __restrict__ s,
                               const float* __restrict__ W1,
                               const float* __restrict__ b1,
                               const float* __restrict__ W2,
                               const float* __restrict__ b2,
                               const float* __restrict__ W3,
                               const float* __restrict__ b3)
{
    __shared__ float smem_m[N_NET];

    const int tid  = threadIdx.x;
    const int k    = tid >> 5;
    const int lane = tid & 31;

    const float x  = s[k & 3];
    const float h1 = fmaxf(fmaf(x, W1[k * HID + lane], b1[k * HID + lane]), 0.0f);

    const float* W2k = W2 + k * HID * HID + lane;
    float a0 = b2[k * HID + lane], a1 = 0.0f, a2 = 0.0f, a3 = 0.0f;
    #pragma unroll
    for (int i = 0; i < HID; i += 4) {
        const float v0 = __shfl_sync(0xFFFFFFFFu, h1, i + 0);
        const float v1 = __shfl_sync(0xFFFFFFFFu, h1, i + 1);
        const float v2 = __shfl_sync(0xFFFFFFFFu, h1, i + 2);
        const float v3 = __shfl_sync(0xFFFFFFFFu, h1, i + 3);
        a0 = fmaf(v0, W2k[(i + 0) * HID], a0);
        a1 = fmaf(v1, W2k[(i + 1) * HID], a1);
        a2 = fmaf(v2, W2k[(i + 2) * HID], a2);
        a3 = fmaf(v3, W2k[(i + 3) * HID], a3);
    }
    const float h2 = fmaxf((a0 + a1) + (a2 + a3), 0.0f);

    float t = h2 * W3[k * HID + lane];
    #pragma unroll
    for (int off = 16; off > 0; off >>= 1)
        t += __shfl_xor_sync(0xFFFFFFFFu, t, off);

    if (lane == 0)
        smem_m[k] = 1.0f / (1.0f + __expf(-(t + b3[k])));
    __syncthreads();

    if (tid == 0) {
        float s0 = 0.0f, s1 = 0.0f;
        #pragma unroll
        for (int i = 0; i < 8; ++i) { s0 += smem_m[i]; s1 += smem_m[8 + i]; }
        // means + 2-way softmax as logistic (s0,s1 in (0,1): exp is safe)
        const float d  = (s1 - s0) * 0.125f;
        const float p0 = 1.0f / (1.0f + __expf(d));
        g_probs[0] = p0;
        g_probs[1] = 1.0f - p0;
        __threadfence();            // make result globally visible
    }
    __syncthreads();                // all threads ordered after the publish
    cudaTriggerProgrammaticLaunchCompletion();
}

// ---------------------------------------------------------------------------
// Secondary (PDL): ramps up concurrently with the primary; waits only at
// griddepsync, then one volatile 8B load + one float4 store per thread.
// 512 blocks x 256 threads x 1 float4 = 131072 float4 = 262144*2 floats.
// ---------------------------------------------------------------------------
__global__ __launch_bounds__(256, 8)
void controller_fill_kernel(float4* __restrict__ out, int n_vec4)
{
    const int idx = blockIdx.x * blockDim.x + threadIdx.x;

    cudaGridDependencySynchronize();

    volatile float* gp = (volatile float*)g_probs;
    const float p0 = gp[0];
    const float p1 = gp[1];

    if (idx < n_vec4)
        out[idx] = make_float4(p0, p1, p0, p1);
}

extern "C" void kernel_launch(void* const* d_in, const int* in_sizes, int n_in,
                              void* d_out, int out_size)
{
    const float* s  = (const float*)d_in[0];
    const float* W1 = (const float*)d_in[1];
    const float* b1 = (const float*)d_in[2];
    const float* W2 = (const float*)d_in[3];
    const float* b2 = (const float*)d_in[4];
    const float* W3 = (const float*)d_in[5];
    const float* b3 = (const float*)d_in[6];

    // Primary: plain launch on the default (captured) stream.
    controller_compute_kernel<<<1, 512>>>(s, W1, b1, W2, b2, W3, b3);

    // Secondary: programmatic dependent launch — overlaps its ramp with the
    // primary's execution; griddepsync provides the ordering + visibility.
    const int n_vec4 = out_size / 4;                 // 131072 for B=262144
    cudaLaunchConfig_t cfg = {};
    cfg.gridDim  = dim3((n_vec4 + 255) / 256, 1, 1); // 512 blocks
    cfg.blockDim = dim3(256, 1, 1);
    cfg.dynamicSmemBytes = 0;
    cfg.stream = 0;

    cudaLaunchAttribute attr[1];
    attr[0].id = cudaLaunchAttributeProgrammaticStreamSerialization;
    attr[0].val.programmaticStreamSerializationAllowed = 1;
    cfg.attrs    = attr;
    cfg.numAttrs = 1;

    cudaLaunchKernelEx(&cfg, controller_fill_kernel, (float4*)d_out, n_vec4);
}

// round 8
// speedup vs baseline: 1.4661x; 1.4661x over previous
#include <cuda_runtime.h>
#include <math.h>

#define N_NET 16
#define HID   32

// Fused: warps 0-15 of every block redundantly evaluate the 16 tiny MLPs on
// s[0]; after one barrier, all 32 warps derive the softmax and store.
// Grid 128 x 1024: 128*1024 threads * 1 float4 = 131072 float4 = 262144*2 floats.
__global__ __launch_bounds__(1024, 1)
void controller_fused_kernel(const float* __restrict__ s,
                             const float* __restrict__ W1,
                             const float* __restrict__ b1,
                             const float* __restrict__ W2,
                             const float* __restrict__ b2,
                             const float* __restrict__ W3,
                             const float* __restrict__ b3,
                             float4* __restrict__ out,
                             int n_vec4)
{
    __shared__ float smem_m[N_NET];

    const int tid  = threadIdx.x;
    const int wid  = tid >> 5;
    const int lane = tid & 31;

    if (wid < N_NET) {
        const int k = wid;                       // network id = warp id
        const float x = s[k & 3];

        // Layer 1
        const float h1 = fmaxf(fmaf(x, W1[k * HID + lane], b1[k * HID + lane]), 0.0f);

        // Layer 2: 4 independent accumulators (chain depth 8), coalesced W2 loads.
        const float* W2k = W2 + k * HID * HID + lane;
        float a0 = b2[k * HID + lane], a1 = 0.0f, a2 = 0.0f, a3 = 0.0f;
        #pragma unroll
        for (int i = 0; i < HID; i += 4) {
            const float v0 = __shfl_sync(0xFFFFFFFFu, h1, i + 0);
            const float v1 = __shfl_sync(0xFFFFFFFFu, h1, i + 1);
            const float v2 = __shfl_sync(0xFFFFFFFFu, h1, i + 2);
            const float v3 = __shfl_sync(0xFFFFFFFFu, h1, i + 3);
            a0 = fmaf(v0, W2k[(i + 0) * HID], a0);
            a1 = fmaf(v1, W2k[(i + 1) * HID], a1);
            a2 = fmaf(v2, W2k[(i + 2) * HID], a2);
            a3 = fmaf(v3, W2k[(i + 3) * HID], a3);
        }
        const float h2 = fmaxf((a0 + a1) + (a2 + a3), 0.0f);

        // Layer 3: warp tree-reduce h2 . W3[k,:,0]
        float t = h2 * W3[k * HID + lane];
        #pragma unroll
        for (int off = 16; off > 0; off >>= 1)
            t += __shfl_xor_sync(0xFFFFFFFFu, t, off);

        if (lane == 0)
            smem_m[k] = 1.0f / (1.0f + __expf(-(t + b3[k])));
    }
    __syncthreads();

    // ---- epilogue (all 32 warps): straight-line, broadcast LDS ----
    float s0 = 0.0f, s1 = 0.0f;
    #pragma unroll
    for (int i = 0; i < 8; ++i) { s0 += smem_m[i]; s1 += smem_m[8 + i]; }
    // means + 2-way softmax as logistic; sums in (0,8) so exp is safe.
    const float d  = (s1 - s0) * 0.125f;
    const float p0 = 1.0f / (1.0f + __expf(d));
    const float p1 = 1.0f - p0;
    const float4 v = make_float4(p0, p1, p0, p1);

    // ---- fill: exactly one float4 per thread, fully coalesced ----
    const int idx = blockIdx.x * 1024 + tid;
    if (idx < n_vec4) out[idx] = v;
}

extern "C" void kernel_launch(void* const* d_in, const int* in_sizes, int n_in,
                              void* d_out, int out_size)
{
    const float* s  = (const float*)d_in[0];
    const float* W1 = (const float*)d_in[1];
    const float* b1 = (const float*)d_in[2];
    const float* W2 = (const float*)d_in[3];
    const float* b2 = (const float*)d_in[4];
    const float* W3 = (const float*)d_in[5];
    const float* b3 = (const float*)d_in[6];

    // out_size = B*2 floats. For B=262144: n_vec4=131072 -> 128 blocks exactly.
    const int n_vec4 = out_size / 4;
    const int blocks = (n_vec4 + 1023) / 1024;   // 1024 threads, 1 float4 each

    controller_fused_kernel<<<blocks, 1024>>>(s, W1, b1, W2, b2, W3, b3,
                                              (float4*)d_out, n_vec4);
}

// round 9
// speedup vs baseline: 1.6040x; 1.0941x over previous
#include <cuda_runtime.h>
#include <math.h>

#define N_NET 16
#define HID   32

// Fused: warps 0-15 of every block redundantly evaluate the 16 tiny MLPs on
// s[0]; after one barrier, all 32 warps derive the softmax and store.
// Grid 128 x 1024: 128*1024 threads * 1 float4 = 131072 float4 = 262144*2 floats.
__global__ __launch_bounds__(1024, 1)
void controller_fused_kernel(const float* __restrict__ s,
                             const float* __restrict__ W1,
                             const float* __restrict__ b1,
                             const float* __restrict__ W2,
                             const float* __restrict__ b2,
                             const float* __restrict__ W3,
                             const float* __restrict__ b3,
                             float4* __restrict__ out,
                             int n_vec4)
{
    __shared__ float smem_m[N_NET];

    const int tid  = threadIdx.x;
    const int wid  = tid >> 5;
    const int lane = tid & 31;

    if (wid < N_NET) {
        const int k = wid;                       // network id = warp id
        const float x = s[k & 3];

        // Layer 1
        const float h1 = fmaxf(fmaf(x, W1[k * HID + lane], b1[k * HID + lane]), 0.0f);

        // Layer 2: 4 independent accumulators (chain depth 8), coalesced W2 loads.
        const float* W2k = W2 + k * HID * HID + lane;
        float a0 = b2[k * HID + lane], a1 = 0.0f, a2 = 0.0f, a3 = 0.0f;
        #pragma unroll
        for (int i = 0; i < HID; i += 4) {
            const float v0 = __shfl_sync(0xFFFFFFFFu, h1, i + 0);
            const float v1 = __shfl_sync(0xFFFFFFFFu, h1, i + 1);
            const float v2 = __shfl_sync(0xFFFFFFFFu, h1, i + 2);
            const float v3 = __shfl_sync(0xFFFFFFFFu, h1, i + 3);
            a0 = fmaf(v0, W2k[(i + 0) * HID], a0);
            a1 = fmaf(v1, W2k[(i + 1) * HID], a1);
            a2 = fmaf(v2, W2k[(i + 2) * HID], a2);
            a3 = fmaf(v3, W2k[(i + 3) * HID], a3);
        }
        const float h2 = fmaxf((a0 + a1) + (a2 + a3), 0.0f);

        // Layer 3: fixed-point s15.16 warp sum in ONE redux.sync.add.s32
        // (|partial| <~ 8, sum <~ 50: no overflow; quant err ~2e-4 abs in t,
        //  ~1e-5 in final output — tolerance is 1e-3).
        const float partial = h2 * W3[k * HID + lane];
        const int   pi      = __float2int_rn(partial * 65536.0f);
        int tsum;
        asm volatile("redux.sync.add.s32 %0, %1, 0xffffffff;"
                     : "=r"(tsum) : "r"(pi));

        if (lane == 0) {
            const float t = (float)tsum * (1.0f / 65536.0f);
            const float z = t + b3[k];
            smem_m[k] = __fdividef(1.0f, 1.0f + __expf(-z));   // fast sigmoid
        }
    }
    __syncthreads();

    // ---- epilogue (all 32 warps): straight-line, broadcast LDS ----
    float s0 = 0.0f, s1 = 0.0f;
    #pragma unroll
    for (int i = 0; i < 8; ++i) { s0 += smem_m[i]; s1 += smem_m[8 + i]; }
    // means + 2-way softmax as logistic; sums in (0,8) so exp is safe.
    const float d  = (s1 - s0) * 0.125f;
    const float p0 = __fdividef(1.0f, 1.0f + __expf(d));
    const float p1 = 1.0f - p0;
    const float4 v = make_float4(p0, p1, p0, p1);

    // ---- fill: exactly one float4 per thread, fully coalesced ----
    const int idx = blockIdx.x * 1024 + tid;
    if (idx < n_vec4) out[idx] = v;
}

extern "C" void kernel_launch(void* const* d_in, const int* in_sizes, int n_in,
                              void* d_out, int out_size)
{
    const float* s  = (const float*)d_in[0];
    const float* W1 = (const float*)d_in[1];
    const float* b1 = (const float*)d_in[2];
    const float* W2 = (const float*)d_in[3];
    const float* b2 = (const float*)d_in[4];
    const float* W3 = (const float*)d_in[5];
    const float* b3 = (const float*)d_in[6];

    // out_size = B*2 floats. For B=262144: n_vec4=131072 -> 128 blocks exactly.
    const int n_vec4 = out_size / 4;
    const int blocks = (n_vec4 + 1023) / 1024;   // 1024 threads, 1 float4 each

    controller_fused_kernel<<<blocks, 1024>>>(s, W1, b1, W2, b2, W3, b3,
                                              (float4*)d_out, n_vec4);
}